// round 5
// baseline (speedup 1.0000x reference)
#include <cuda_runtime.h>
#include <cuda_bf16.h>
#include <math.h>

typedef unsigned long long ull;
#define TT 512
#define BBATCH 64
#define NLAB 34
#define NEGV -10000.0f
#define NBLK 128

__device__ float g_xg[2][TT][BBATCH][1024];
__device__ float g_h[2][TT][BBATCH][256];
__device__ float g_feats[TT][BBATCH][NLAB];
__device__ unsigned g_bar = 0, g_done = 0;

__device__ __forceinline__ ull ffma2(ull a, ull b, ull c) {
    ull d; asm("fma.rn.f32x2 %0,%1,%2,%3;" : "=l"(d) : "l"(a), "l"(b), "l"(c)); return d;
}
__device__ __forceinline__ float hsum2(ull a) {
    return __uint_as_float((unsigned)a) + __uint_as_float((unsigned)(a >> 32));
}
__device__ __forceinline__ float sigf(float x) { return 1.f / (1.f + expf(-x)); }

// ============ Kernel 1: embedding gather + input GEMM ============
// C[r][jg]=dot(embed[sent(r)],Wih_d[col])+bih+bhh ; r=t*64+b, jg: dir=jg>>10
#define IG_SMEM ((128 * 132 + 128 * 130) * 4)
__global__ void __launch_bounds__(256, 1) ig_kernel(
    const int* __restrict__ sent, const float* __restrict__ embed,
    const float* __restrict__ Wih_f, const float* __restrict__ Wih_b,
    const float* __restrict__ bih_f, const float* __restrict__ bhh_f,
    const float* __restrict__ bih_b, const float* __restrict__ bhh_b)
{
    extern __shared__ float sm[];
    float* As = sm;               // [128][132]
    float* Ws = sm + 128 * 132;   // [128][130]
    __shared__ int ssm[128];
    int tid = threadIdx.x;
    int row0 = blockIdx.x * 128, jg0 = blockIdx.y * 128;
    int dir = jg0 >> 10, col0 = jg0 & 1023;
    const float* W = dir ? Wih_b : Wih_f;
    const float* bA = dir ? bih_b : bih_f;
    const float* bB = dir ? bhh_b : bhh_f;
    if (tid < 128) { int r = row0 + tid; ssm[tid] = sent[(r & 63) * TT + (r >> 6)]; }

    ull acc[8][8];
#pragma unroll
    for (int i = 0; i < 8; ++i)
#pragma unroll
        for (int j = 0; j < 8; ++j) acc[i][j] = 0ull;
    int ty = tid >> 4, tx = tid & 15;

    for (int kc = 0; kc < 2; ++kc) {
        int k0 = kc * 128;
        __syncthreads();
#pragma unroll
        for (int it = 0; it < 16; ++it) {
            int idx = it * 256 + tid, r = idx >> 5, k4 = idx & 31;
            *(float4*)(As + r * 132 + k4 * 4) =
                *(const float4*)(embed + (size_t)ssm[r] * 256 + k0 + k4 * 4);
        }
#pragma unroll
        for (int it = 0; it < 16; ++it) {
            int idx = it * 256 + tid, c = idx >> 5, k4 = idx & 31;
            float4 v = *(const float4*)(W + (size_t)(col0 + c) * 256 + k0 + k4 * 4);
            *(float2*)(Ws + c * 130 + k4 * 4) = make_float2(v.x, v.y);
            *(float2*)(Ws + c * 130 + k4 * 4 + 2) = make_float2(v.z, v.w);
        }
        __syncthreads();
#pragma unroll 2
        for (int kp = 0; kp < 64; ++kp) {
            ull a[8], w[8];
#pragma unroll
            for (int i = 0; i < 8; ++i) a[i] = *(const ull*)(As + (ty + 16 * i) * 132 + kp * 2);
#pragma unroll
            for (int j = 0; j < 8; ++j) w[j] = *(const ull*)(Ws + (tx + 16 * j) * 130 + kp * 2);
#pragma unroll
            for (int i = 0; i < 8; ++i)
#pragma unroll
                for (int j = 0; j < 8; ++j) acc[i][j] = ffma2(a[i], w[j], acc[i][j]);
        }
    }
#pragma unroll
    for (int i = 0; i < 8; ++i) {
        int r = row0 + ty + 16 * i, t = r >> 6, b = r & 63;
#pragma unroll
        for (int j = 0; j < 8; ++j) {
            int c = col0 + tx + 16 * j;
            g_xg[dir][t][b][c] = hsum2(acc[i][j]) + bA[c] + bB[c];
        }
    }
}

// ============ Kernel 2: persistent BiLSTM recurrence ============
// 128 blocks: dir=bid>>6, block owns 4 units u0..u0+3 (16 gate rows, rr=(g<<2)|lu)
#define REC_SMEM ((64 * 260 + 16 * 260 + 16 * 68) * 4)
__global__ void __launch_bounds__(256, 1) rec_kernel(
    const float* __restrict__ Whh_f, const float* __restrict__ Whh_b,
    const float* __restrict__ h0, const float* __restrict__ c0)
{
    extern __shared__ float sm[];
    float* hs = sm;                 // [64][260]
    float* ws = sm + 64 * 260;      // [16][260]
    float* ps = ws + 16 * 260;      // [16][68]
    int tid = threadIdx.x, bid = blockIdx.x;
    int dir = bid >> 6, u0 = (bid & 63) * 4;
    const float* W = dir ? Whh_b : Whh_f;

    for (int s = tid; s < 16 * 128; s += 256) {
        int rr = s >> 7, k2 = s & 127;
        *(float2*)(ws + rr * 260 + 2 * k2) =
            *(const float2*)(W + (size_t)((rr >> 2) * 256 + u0 + (rr & 3)) * 256 + 2 * k2);
    }
    int cb = tid & 63, clu = tid >> 6;                    // cell-update (b,lu)
    float c = c0[(dir * BBATCH + cb) * 256 + u0 + clu];
    int lane = tid & 31, wrp = tid >> 5;
    int rr = lane & 15, bh = lane >> 4;
    int b0 = bh * 32 + wrp * 4;                           // this thread: rr x b0..b0+3

    for (int s = 0; s < TT; ++s) {
        int t = dir ? TT - 1 - s : s;
        const float* hsrc = (s == 0) ? h0 + (size_t)dir * BBATCH * 256
                                     : &g_h[dir][dir ? t + 1 : t - 1][0][0];
        for (int p = tid; p < 64 * 128; p += 256)
            *(float2*)(hs + (p >> 7) * 260 + 2 * (p & 127)) =
                *(const float2*)(hsrc + (p >> 7) * 256 + 2 * (p & 127));
        __syncthreads();
        {
            ull a0 = 0, a1 = 0, a2 = 0, a3 = 0;
            const float* wp = ws + rr * 260;
            const float* hp = hs + b0 * 260;
#pragma unroll 8
            for (int q = 0; q < 64; ++q) {
                ulonglong2 wv = *(const ulonglong2*)(wp + 4 * q);
                ulonglong2 h0v = *(const ulonglong2*)(hp + 4 * q);
                ulonglong2 h1v = *(const ulonglong2*)(hp + 260 + 4 * q);
                ulonglong2 h2v = *(const ulonglong2*)(hp + 520 + 4 * q);
                ulonglong2 h3v = *(const ulonglong2*)(hp + 780 + 4 * q);
                a0 = ffma2(h0v.x, wv.x, a0); a0 = ffma2(h0v.y, wv.y, a0);
                a1 = ffma2(h1v.x, wv.x, a1); a1 = ffma2(h1v.y, wv.y, a1);
                a2 = ffma2(h2v.x, wv.x, a2); a2 = ffma2(h2v.y, wv.y, a2);
                a3 = ffma2(h3v.x, wv.x, a3); a3 = ffma2(h3v.y, wv.y, a3);
            }
            ps[rr * 68 + b0] = hsum2(a0); ps[rr * 68 + b0 + 1] = hsum2(a1);
            ps[rr * 68 + b0 + 2] = hsum2(a2); ps[rr * 68 + b0 + 3] = hsum2(a3);
        }
        __syncthreads();
        {
            const float* xg = &g_xg[dir][t][cb][0];
            float gi = ps[(0 | clu) * 68 + cb] + xg[0 * 256 + u0 + clu];
            float gf = ps[(4 | clu) * 68 + cb] + xg[1 * 256 + u0 + clu];
            float gg = ps[(8 | clu) * 68 + cb] + xg[2 * 256 + u0 + clu];
            float go = ps[(12 | clu) * 68 + cb] + xg[3 * 256 + u0 + clu];
            c = sigf(gf) * c + sigf(gi) * tanhf(gg);
            g_h[dir][t][cb][u0 + clu] = sigf(go) * tanhf(c);
        }
        __threadfence();
        __syncthreads();
        if (tid == 0) {
            atomicAdd(&g_bar, 1u);
            unsigned tgt = (unsigned)(s + 1) * NBLK;
            while (atomicAdd(&g_bar, 0u) < tgt) {}
        }
        __syncthreads();
    }
    if (tid == 0 && atomicAdd(&g_done, 1u) == NBLK - 1) {
        g_bar = 0u; g_done = 0u; __threadfence();
    }
}

// ============ Kernel 3: feats = [hf|hb] @ W_out.T + b_out ============
#define FE_SMEM ((64 * 520 + 34 * 520) * 4)
__global__ void __launch_bounds__(256, 1) feats_kernel(
    const float* __restrict__ W_out, const float* __restrict__ b_out)
{
    extern __shared__ float sm[];
    float* hc = sm;               // [64][520] : hf(256)|hb(256)
    float* wo = sm + 64 * 520;    // [34][520]
    int t = blockIdx.x, tid = threadIdx.x;
    for (int p = tid; p < 64 * 256; p += 256) {
        int b = p >> 8, k = p & 255;
        hc[b * 520 + k] = g_h[0][t][b][k];
        hc[b * 520 + 256 + k] = g_h[1][t][b][k];
    }
    for (int p = tid; p < 34 * 512; p += 256)
        wo[(p >> 9) * 520 + (p & 511)] = W_out[p];
    __syncthreads();
    for (int it = tid; it < 64 * 17; it += 256) {
        int b = it / 17, j0 = (it % 17) * 2, j1 = j0 + 1;
        ull a0 = 0, a1 = 0;
        const float* hp = hc + b * 520;
        const float* w0 = wo + j0 * 520;
        const float* w1 = wo + j1 * 520;
#pragma unroll 4
        for (int kp = 0; kp < 256; ++kp) {
            ull hv = *(const ull*)(hp + 2 * kp);
            a0 = ffma2(hv, *(const ull*)(w0 + 2 * kp), a0);
            a1 = ffma2(hv, *(const ull*)(w1 + 2 * kp), a1);
        }
        g_feats[t][b][j0] = hsum2(a0) + b_out[j0];
        g_feats[t][b][j1] = hsum2(a1) + b_out[j1];
    }
}

// ============ Kernel 4: Viterbi + backtrack (block per batch) ============
__global__ void vit_kernel(const float* __restrict__ trans, float* out, int osz)
{
    __shared__ float tT[34][36];           // tT[j][k] = trans[k][j]
    __shared__ float dp[34], ndp[34];
    __shared__ unsigned char par[TT][34];
    int b = blockIdx.x, tid = threadIdx.x;
    for (int p = tid; p < 34 * 34; p += 64) tT[p % 34][p / 34] = trans[p];
    if (tid < 34) dp[tid] = (tid == 32) ? 0.f : NEGV;
    __syncthreads();
    for (int t = 0; t < TT; ++t) {
        if (tid < 34) {
            float best = -1e30f; int arg = 0;
#pragma unroll 2
            for (int k = 0; k < 34; ++k) {
                float v = dp[k] + tT[tid][k];
                if (v > best) { best = v; arg = k; }
            }
            par[t][tid] = (unsigned char)arg;
            ndp[tid] = best + g_feats[t][b][tid];
        }
        __syncthreads();
        if (tid < 34) dp[tid] = ndp[tid];
        __syncthreads();
    }
    if (tid == 0) {
        float best = -1e30f; int lab = 0;
        for (int j = 0; j < 34; ++j) {
            float v = dp[j] + tT[33][j];   // trans[j][STOP]
            if (v > best) { best = v; lab = j; }
        }
        float* pp;
        if (osz >= BBATCH + BBATCH * TT) { out[b] = best; pp = out + BBATCH + (size_t)b * TT; }
        else if (osz >= BBATCH * TT)     { pp = out + (size_t)b * TT; }
        else                             { out[b] = best; return; }
        int l = lab;
        for (int t = TT - 1; t >= 0; --t) { pp[t] = (float)l; l = par[t][l]; }
    }
}

extern "C" void kernel_launch(void* const* d_in, const int* in_sizes, int n_in,
                              void* d_out, int out_size) {
    const int*   sent  = (const int*)d_in[0];
    const float* embed = (const float*)d_in[2];
    const float* Wih_f = (const float*)d_in[3];
    const float* Whh_f = (const float*)d_in[4];
    const float* bih_f = (const float*)d_in[5];
    const float* bhh_f = (const float*)d_in[6];
    const float* Wih_b = (const float*)d_in[7];
    const float* Whh_b = (const float*)d_in[8];
    const float* bih_b = (const float*)d_in[9];
    const float* bhh_b = (const float*)d_in[10];
    const float* h0    = (const float*)d_in[11];
    const float* c0    = (const float*)d_in[12];
    const float* W_out = (const float*)d_in[13];
    const float* b_out = (const float*)d_in[14];
    const float* trans = (const float*)d_in[15];

    cudaFuncSetAttribute(ig_kernel, cudaFuncAttributeMaxDynamicSharedMemorySize, IG_SMEM);
    cudaFuncSetAttribute(rec_kernel, cudaFuncAttributeMaxDynamicSharedMemorySize, REC_SMEM);
    cudaFuncSetAttribute(feats_kernel, cudaFuncAttributeMaxDynamicSharedMemorySize, FE_SMEM);

    ig_kernel<<<dim3(256, 16), 256, IG_SMEM>>>(sent, embed, Wih_f, Wih_b,
                                               bih_f, bhh_f, bih_b, bhh_b);
    rec_kernel<<<NBLK, 256, REC_SMEM>>>(Whh_f, Whh_b, h0, c0);
    feats_kernel<<<TT, 256, FE_SMEM>>>(W_out, b_out);
    vit_kernel<<<BBATCH, 64>>>(trans, (float*)d_out, out_size);
}

// round 9
// speedup vs baseline: 1.0666x; 1.0666x over previous
#include <cuda_runtime.h>
#include <cuda_bf16.h>
#include <math.h>

typedef unsigned long long ull;
#define TT 512
#define BBATCH 64
#define NLAB 34
#define NEGV -10000.0f
#define NBLK 128

__device__ float g_xg[2][TT][BBATCH][1024];
__device__ float g_h[2][TT][BBATCH][256];
__device__ float g_feats[TT][BBATCH][NLAB];
__device__ unsigned g_bar = 0, g_done = 0;

__device__ __forceinline__ ull ffma2(ull a, ull b, ull c) {
    ull d; asm("fma.rn.f32x2 %0,%1,%2,%3;" : "=l"(d) : "l"(a), "l"(b), "l"(c)); return d;
}
__device__ __forceinline__ float hsum2(ull a) {
    return __uint_as_float((unsigned)a) + __uint_as_float((unsigned)(a >> 32));
}
__device__ __forceinline__ float sigf(float x) { return 1.f / (1.f + expf(-x)); }

// ============ Kernel 1: embedding gather + input GEMM ============
#define IG_SMEM ((128 * 132 + 128 * 130) * 4)
__global__ void __launch_bounds__(256, 1) ig_kernel(
    const int* __restrict__ sent, const float* __restrict__ embed,
    const float* __restrict__ Wih_f, const float* __restrict__ Wih_b,
    const float* __restrict__ bih_f, const float* __restrict__ bhh_f,
    const float* __restrict__ bih_b, const float* __restrict__ bhh_b)
{
    extern __shared__ float sm[];
    float* As = sm;               // [128][132]
    float* Ws = sm + 128 * 132;   // [128][130]
    __shared__ int ssm[128];
    int tid = threadIdx.x;
    int row0 = blockIdx.x * 128, jg0 = blockIdx.y * 128;
    int dir = jg0 >> 10, col0 = jg0 & 1023;
    const float* W = dir ? Wih_b : Wih_f;
    const float* bA = dir ? bih_b : bih_f;
    const float* bB = dir ? bhh_b : bhh_f;
    if (tid < 128) { int r = row0 + tid; ssm[tid] = sent[(r & 63) * TT + (r >> 6)]; }

    ull acc[8][8];
#pragma unroll
    for (int i = 0; i < 8; ++i)
#pragma unroll
        for (int j = 0; j < 8; ++j) acc[i][j] = 0ull;
    int ty = tid >> 4, tx = tid & 15;

    for (int kc = 0; kc < 2; ++kc) {
        int k0 = kc * 128;
        __syncthreads();
#pragma unroll
        for (int it = 0; it < 16; ++it) {
            int idx = it * 256 + tid, r = idx >> 5, k4 = idx & 31;
            *(float4*)(As + r * 132 + k4 * 4) =
                *(const float4*)(embed + (size_t)ssm[r] * 256 + k0 + k4 * 4);
        }
#pragma unroll
        for (int it = 0; it < 16; ++it) {
            int idx = it * 256 + tid, c = idx >> 5, k4 = idx & 31;
            float4 v = *(const float4*)(W + (size_t)(col0 + c) * 256 + k0 + k4 * 4);
            *(float2*)(Ws + c * 130 + k4 * 4) = make_float2(v.x, v.y);
            *(float2*)(Ws + c * 130 + k4 * 4 + 2) = make_float2(v.z, v.w);
        }
        __syncthreads();
#pragma unroll 2
        for (int kp = 0; kp < 64; ++kp) {
            ull a[8], w[8];
#pragma unroll
            for (int i = 0; i < 8; ++i) a[i] = *(const ull*)(As + (ty + 16 * i) * 132 + kp * 2);
#pragma unroll
            for (int j = 0; j < 8; ++j) w[j] = *(const ull*)(Ws + (tx + 16 * j) * 130 + kp * 2);
#pragma unroll
            for (int i = 0; i < 8; ++i)
#pragma unroll
                for (int j = 0; j < 8; ++j) acc[i][j] = ffma2(a[i], w[j], acc[i][j]);
        }
    }
#pragma unroll
    for (int i = 0; i < 8; ++i) {
        int r = row0 + ty + 16 * i, t = r >> 6, b = r & 63;
#pragma unroll
        for (int j = 0; j < 8; ++j) {
            int c = col0 + tx + 16 * j;
            g_xg[dir][t][b][c] = hsum2(acc[i][j]) + bA[c] + bB[c];
        }
    }
}

// ============ Kernel 2: persistent BiLSTM recurrence (EXACT R4 text) ============
#define REC_SMEM ((64 * 260 + 16 * 260 + 16 * 68) * 4)
__global__ void __launch_bounds__(256, 1) rec_kernel(
    const float* __restrict__ Whh_f, const float* __restrict__ Whh_b,
    const float* __restrict__ h0, const float* __restrict__ c0)
{
    extern __shared__ float sm[];
    float* hs = sm;                 // [64][260]
    float* ws = sm + 64 * 260;      // [16][260]
    float* ps = ws + 16 * 260;      // [16][68]
    int tid = threadIdx.x, bid = blockIdx.x;
    int dir = bid >> 6, u0 = (bid & 63) * 4;
    const float* W = dir ? Whh_b : Whh_f;

    for (int s = tid; s < 16 * 128; s += 256) {
        int rr = s >> 7, k2 = s & 127;
        *(float2*)(ws + rr * 260 + 2 * k2) =
            *(const float2*)(W + (size_t)((rr >> 2) * 256 + u0 + (rr & 3)) * 256 + 2 * k2);
    }
    int cb = tid & 63, clu = tid >> 6;                    // cell-update (b,lu)
    float c = c0[(dir * BBATCH + cb) * 256 + u0 + clu];
    int lane = tid & 31, wrp = tid >> 5;
    int rr = lane & 15, bh = lane >> 4;
    int b0 = bh * 32 + wrp * 4;                           // this thread: rr x b0..b0+3

    for (int s = 0; s < TT; ++s) {
        int t = dir ? TT - 1 - s : s;
        const float* hsrc = (s == 0) ? h0 + (size_t)dir * BBATCH * 256
                                     : &g_h[dir][dir ? t + 1 : t - 1][0][0];
        for (int p = tid; p < 64 * 128; p += 256)
            *(float2*)(hs + (p >> 7) * 260 + 2 * (p & 127)) =
                *(const float2*)(hsrc + (p >> 7) * 256 + 2 * (p & 127));
        __syncthreads();
        {
            ull a0 = 0, a1 = 0, a2 = 0, a3 = 0;
            const float* wp = ws + rr * 260;
            const float* hp = hs + b0 * 260;
#pragma unroll 8
            for (int q = 0; q < 64; ++q) {
                ulonglong2 wv = *(const ulonglong2*)(wp + 4 * q);
                ulonglong2 h0v = *(const ulonglong2*)(hp + 4 * q);
                ulonglong2 h1v = *(const ulonglong2*)(hp + 260 + 4 * q);
                ulonglong2 h2v = *(const ulonglong2*)(hp + 520 + 4 * q);
                ulonglong2 h3v = *(const ulonglong2*)(hp + 780 + 4 * q);
                a0 = ffma2(h0v.x, wv.x, a0); a0 = ffma2(h0v.y, wv.y, a0);
                a1 = ffma2(h1v.x, wv.x, a1); a1 = ffma2(h1v.y, wv.y, a1);
                a2 = ffma2(h2v.x, wv.x, a2); a2 = ffma2(h2v.y, wv.y, a2);
                a3 = ffma2(h3v.x, wv.x, a3); a3 = ffma2(h3v.y, wv.y, a3);
            }
            ps[rr * 68 + b0] = hsum2(a0); ps[rr * 68 + b0 + 1] = hsum2(a1);
            ps[rr * 68 + b0 + 2] = hsum2(a2); ps[rr * 68 + b0 + 3] = hsum2(a3);
        }
        __syncthreads();
        {
            const float* xg = &g_xg[dir][t][cb][0];
            float gi = ps[(0 | clu) * 68 + cb] + xg[0 * 256 + u0 + clu];
            float gf = ps[(4 | clu) * 68 + cb] + xg[1 * 256 + u0 + clu];
            float gg = ps[(8 | clu) * 68 + cb] + xg[2 * 256 + u0 + clu];
            float go = ps[(12 | clu) * 68 + cb] + xg[3 * 256 + u0 + clu];
            c = sigf(gf) * c + sigf(gi) * tanhf(gg);
            g_h[dir][t][cb][u0 + clu] = sigf(go) * tanhf(c);
        }
        __threadfence();
        __syncthreads();
        if (tid == 0) {
            atomicAdd(&g_bar, 1u);
            unsigned tgt = (unsigned)(s + 1) * NBLK;
            while (atomicAdd(&g_bar, 0u) < tgt) {}
        }
        __syncthreads();
    }
    if (tid == 0 && atomicAdd(&g_done, 1u) == NBLK - 1) {
        g_bar = 0u; g_done = 0u; __threadfence();
    }
}

// ============ Kernel 3: feats = [hf|hb] @ W_out.T + b_out ============
#define FE_SMEM ((64 * 520 + 34 * 520) * 4)
__global__ void __launch_bounds__(256, 1) feats_kernel(
    const float* __restrict__ W_out, const float* __restrict__ b_out)
{
    extern __shared__ float sm[];
    float* hc = sm;               // [64][520]
    float* wo = sm + 64 * 520;    // [34][520]
    int t = blockIdx.x, tid = threadIdx.x;
    for (int p = tid; p < 64 * 256; p += 256) {
        int b = p >> 8, k = p & 255;
        hc[b * 520 + k] = g_h[0][t][b][k];
        hc[b * 520 + 256 + k] = g_h[1][t][b][k];
    }
    for (int p = tid; p < 34 * 512; p += 256)
        wo[(p >> 9) * 520 + (p & 511)] = W_out[p];
    __syncthreads();
    for (int it = tid; it < 64 * 17; it += 256) {
        int b = it / 17, j0 = (it % 17) * 2, j1 = j0 + 1;
        ull a0 = 0, a1 = 0;
        const float* hp = hc + b * 520;
        const float* w0 = wo + j0 * 520;
        const float* w1 = wo + j1 * 520;
#pragma unroll 4
        for (int kp = 0; kp < 256; ++kp) {
            ull hv = *(const ull*)(hp + 2 * kp);
            a0 = ffma2(hv, *(const ull*)(w0 + 2 * kp), a0);
            a1 = ffma2(hv, *(const ull*)(w1 + 2 * kp), a1);
        }
        g_feats[t][b][j0] = hsum2(a0) + b_out[j0];
        g_feats[t][b][j1] = hsum2(a1) + b_out[j1];
    }
}

// ============ Kernel 4: Viterbi + backtrack (block per batch, new fast version) ============
__global__ void __launch_bounds__(64) vit_kernel(
    const float* __restrict__ trans, float* out, int osz)
{
    __shared__ float tT[34 * 35];          // tT[j*35+k] = trans[k][j]
    __shared__ float dp[2][40];
    __shared__ unsigned char par[TT][34];
    int b = blockIdx.x, tid = threadIdx.x;
    for (int p = tid; p < 34 * 34; p += 64) tT[(p % 34) * 35 + (p / 34)] = trans[p];
    if (tid < 34) dp[0][tid] = (tid == 32) ? 0.f : NEGV;
    __syncthreads();

    float f = (tid < 34) ? g_feats[0][b][tid] : 0.f;
    int cur = 0;
    for (int t = 0; t < TT; ++t) {
        float fn = (tid < 34 && t < TT - 1) ? g_feats[t + 1][b][tid] : 0.f;
        if (tid < 34) {
            const float* tr = tT + tid * 35;
            const float* d = dp[cur];
            float be = d[0] + tr[0], bo = d[1] + tr[1];
            int ae = 0, ao = 1;
#pragma unroll
            for (int k = 2; k < 34; k += 2) {
                float ve = d[k] + tr[k];
                float vo = d[k + 1] + tr[k + 1];
                if (ve > be) { be = ve; ae = k; }
                if (vo > bo) { bo = vo; ao = k + 1; }
            }
            float best = be; int arg = ae;
            if (bo > be || (bo == be && ao < ae)) { best = bo; arg = ao; }
            par[t][tid] = (unsigned char)arg;
            dp[cur ^ 1][tid] = best + f;
        }
        f = fn;
        cur ^= 1;
        __syncthreads();
    }
    if (tid == 0) {
        float best = -1e30f; int lab = 0;
        const float* d = dp[cur];
        for (int j = 0; j < 34; ++j) {
            float v = d[j] + tT[33 * 35 + j];   // + trans[j][STOP]
            if (v > best) { best = v; lab = j; }
        }
        float* pp;
        if (osz >= BBATCH + BBATCH * TT) { out[b] = best; pp = out + BBATCH + (size_t)b * TT; }
        else if (osz >= BBATCH * TT)     { pp = out + (size_t)b * TT; }
        else                             { out[b] = best; return; }
        int l = lab;
        for (int t = TT - 1; t >= 0; --t) { pp[t] = (float)l; l = par[t][l]; }
    }
}

extern "C" void kernel_launch(void* const* d_in, const int* in_sizes, int n_in,
                              void* d_out, int out_size) {
    const int*   sent  = (const int*)d_in[0];
    const float* embed = (const float*)d_in[2];
    const float* Wih_f = (const float*)d_in[3];
    const float* Whh_f = (const float*)d_in[4];
    const float* bih_f = (const float*)d_in[5];
    const float* bhh_f = (const float*)d_in[6];
    const float* Wih_b = (const float*)d_in[7];
    const float* Whh_b = (const float*)d_in[8];
    const float* bih_b = (const float*)d_in[9];
    const float* bhh_b = (const float*)d_in[10];
    const float* h0    = (const float*)d_in[11];
    const float* c0    = (const float*)d_in[12];
    const float* W_out = (const float*)d_in[13];
    const float* b_out = (const float*)d_in[14];
    const float* trans = (const float*)d_in[15];

    cudaFuncSetAttribute(ig_kernel, cudaFuncAttributeMaxDynamicSharedMemorySize, IG_SMEM);
    cudaFuncSetAttribute(rec_kernel, cudaFuncAttributeMaxDynamicSharedMemorySize, REC_SMEM);
    cudaFuncSetAttribute(feats_kernel, cudaFuncAttributeMaxDynamicSharedMemorySize, FE_SMEM);

    ig_kernel<<<dim3(256, 16), 256, IG_SMEM>>>(sent, embed, Wih_f, Wih_b,
                                               bih_f, bhh_f, bih_b, bhh_b);
    rec_kernel<<<NBLK, 256, REC_SMEM>>>(Whh_f, Whh_b, h0, c0);
    feats_kernel<<<TT, 256, FE_SMEM>>>(W_out, b_out);
    vit_kernel<<<BBATCH, 64>>>(trans, (float*)d_out, out_size);
}

// round 10
// speedup vs baseline: 1.0924x; 1.0242x over previous
#include <cuda_runtime.h>
#include <cuda_bf16.h>
#include <math.h>

typedef unsigned long long ull;
#define TT 512
#define BBATCH 64
#define NLAB 34
#define NEGV -10000.0f
#define NBLK 128

__device__ float g_xg[2][TT][BBATCH][1024];
__device__ float g_h[2][TT][BBATCH][256];
__device__ float g_feats[TT][BBATCH][NLAB];
__device__ unsigned g_bar = 0, g_done = 0;

__device__ __forceinline__ ull ffma2(ull a, ull b, ull c) {
    ull d; asm("fma.rn.f32x2 %0,%1,%2,%3;" : "=l"(d) : "l"(a), "l"(b), "l"(c)); return d;
}
__device__ __forceinline__ float hsum2(ull a) {
    return __uint_as_float((unsigned)a) + __uint_as_float((unsigned)(a >> 32));
}
__device__ __forceinline__ float sigf(float x) { return 1.f / (1.f + expf(-x)); }
__device__ __forceinline__ unsigned ldcg(const unsigned* p) {
    unsigned v; asm volatile("ld.global.cg.u32 %0,[%1];" : "=r"(v) : "l"(p) : "memory");
    return v;
}

// ============ Kernel 1: embedding gather + input GEMM ============
#define IG_SMEM ((128 * 132 + 128 * 130) * 4)
__global__ void __launch_bounds__(256, 1) ig_kernel(
    const int* __restrict__ sent, const float* __restrict__ embed,
    const float* __restrict__ Wih_f, const float* __restrict__ Wih_b,
    const float* __restrict__ bih_f, const float* __restrict__ bhh_f,
    const float* __restrict__ bih_b, const float* __restrict__ bhh_b)
{
    extern __shared__ float sm[];
    float* As = sm;               // [128][132]
    float* Ws = sm + 128 * 132;   // [128][130]
    __shared__ int ssm[128];
    int tid = threadIdx.x;
    int row0 = blockIdx.x * 128, jg0 = blockIdx.y * 128;
    int dir = jg0 >> 10, col0 = jg0 & 1023;
    const float* W = dir ? Wih_b : Wih_f;
    const float* bA = dir ? bih_b : bih_f;
    const float* bB = dir ? bhh_b : bhh_f;
    if (tid < 128) { int r = row0 + tid; ssm[tid] = sent[(r & 63) * TT + (r >> 6)]; }

    ull acc[8][8];
#pragma unroll
    for (int i = 0; i < 8; ++i)
#pragma unroll
        for (int j = 0; j < 8; ++j) acc[i][j] = 0ull;
    int ty = tid >> 4, tx = tid & 15;

    for (int kc = 0; kc < 2; ++kc) {
        int k0 = kc * 128;
        __syncthreads();
#pragma unroll
        for (int it = 0; it < 16; ++it) {
            int idx = it * 256 + tid, r = idx >> 5, k4 = idx & 31;
            *(float4*)(As + r * 132 + k4 * 4) =
                *(const float4*)(embed + (size_t)ssm[r] * 256 + k0 + k4 * 4);
        }
#pragma unroll
        for (int it = 0; it < 16; ++it) {
            int idx = it * 256 + tid, c = idx >> 5, k4 = idx & 31;
            float4 v = *(const float4*)(W + (size_t)(col0 + c) * 256 + k0 + k4 * 4);
            *(float2*)(Ws + c * 130 + k4 * 4) = make_float2(v.x, v.y);
            *(float2*)(Ws + c * 130 + k4 * 4 + 2) = make_float2(v.z, v.w);
        }
        __syncthreads();
#pragma unroll 2
        for (int kp = 0; kp < 64; ++kp) {
            ull a[8], w[8];
#pragma unroll
            for (int i = 0; i < 8; ++i) a[i] = *(const ull*)(As + (ty + 16 * i) * 132 + kp * 2);
#pragma unroll
            for (int j = 0; j < 8; ++j) w[j] = *(const ull*)(Ws + (tx + 16 * j) * 130 + kp * 2);
#pragma unroll
            for (int i = 0; i < 8; ++i)
#pragma unroll
                for (int j = 0; j < 8; ++j) acc[i][j] = ffma2(a[i], w[j], acc[i][j]);
        }
    }
#pragma unroll
    for (int i = 0; i < 8; ++i) {
        int r = row0 + ty + 16 * i, t = r >> 6, b = r & 63;
#pragma unroll
        for (int j = 0; j < 8; ++j) {
            int c = col0 + tx + 16 * j;
            g_xg[dir][t][b][c] = hsum2(acc[i][j]) + bA[c] + bB[c];
        }
    }
}

// ============ Kernel 2: persistent BiLSTM recurrence ============
// EXACT R4/R8 text except the barrier spin: ld.cg poll + confirming RMW.
#define REC_SMEM ((64 * 260 + 16 * 260 + 16 * 68) * 4)
__global__ void __launch_bounds__(256, 1) rec_kernel(
    const float* __restrict__ Whh_f, const float* __restrict__ Whh_b,
    const float* __restrict__ h0, const float* __restrict__ c0)
{
    extern __shared__ float sm[];
    float* hs = sm;                 // [64][260]
    float* ws = sm + 64 * 260;      // [16][260]
    float* ps = ws + 16 * 260;      // [16][68]
    int tid = threadIdx.x, bid = blockIdx.x;
    int dir = bid >> 6, u0 = (bid & 63) * 4;
    const float* W = dir ? Whh_b : Whh_f;

    for (int s = tid; s < 16 * 128; s += 256) {
        int rr = s >> 7, k2 = s & 127;
        *(float2*)(ws + rr * 260 + 2 * k2) =
            *(const float2*)(W + (size_t)((rr >> 2) * 256 + u0 + (rr & 3)) * 256 + 2 * k2);
    }
    int cb = tid & 63, clu = tid >> 6;                    // cell-update (b,lu)
    float c = c0[(dir * BBATCH + cb) * 256 + u0 + clu];
    int lane = tid & 31, wrp = tid >> 5;
    int rr = lane & 15, bh = lane >> 4;
    int b0 = bh * 32 + wrp * 4;                           // this thread: rr x b0..b0+3

    for (int s = 0; s < TT; ++s) {
        int t = dir ? TT - 1 - s : s;
        const float* hsrc = (s == 0) ? h0 + (size_t)dir * BBATCH * 256
                                     : &g_h[dir][dir ? t + 1 : t - 1][0][0];
        for (int p = tid; p < 64 * 128; p += 256)
            *(float2*)(hs + (p >> 7) * 260 + 2 * (p & 127)) =
                *(const float2*)(hsrc + (p >> 7) * 256 + 2 * (p & 127));
        __syncthreads();
        {
            ull a0 = 0, a1 = 0, a2 = 0, a3 = 0;
            const float* wp = ws + rr * 260;
            const float* hp = hs + b0 * 260;
#pragma unroll 8
            for (int q = 0; q < 64; ++q) {
                ulonglong2 wv = *(const ulonglong2*)(wp + 4 * q);
                ulonglong2 h0v = *(const ulonglong2*)(hp + 4 * q);
                ulonglong2 h1v = *(const ulonglong2*)(hp + 260 + 4 * q);
                ulonglong2 h2v = *(const ulonglong2*)(hp + 520 + 4 * q);
                ulonglong2 h3v = *(const ulonglong2*)(hp + 780 + 4 * q);
                a0 = ffma2(h0v.x, wv.x, a0); a0 = ffma2(h0v.y, wv.y, a0);
                a1 = ffma2(h1v.x, wv.x, a1); a1 = ffma2(h1v.y, wv.y, a1);
                a2 = ffma2(h2v.x, wv.x, a2); a2 = ffma2(h2v.y, wv.y, a2);
                a3 = ffma2(h3v.x, wv.x, a3); a3 = ffma2(h3v.y, wv.y, a3);
            }
            ps[rr * 68 + b0] = hsum2(a0); ps[rr * 68 + b0 + 1] = hsum2(a1);
            ps[rr * 68 + b0 + 2] = hsum2(a2); ps[rr * 68 + b0 + 3] = hsum2(a3);
        }
        __syncthreads();
        {
            const float* xg = &g_xg[dir][t][cb][0];
            float gi = ps[(0 | clu) * 68 + cb] + xg[0 * 256 + u0 + clu];
            float gf = ps[(4 | clu) * 68 + cb] + xg[1 * 256 + u0 + clu];
            float gg = ps[(8 | clu) * 68 + cb] + xg[2 * 256 + u0 + clu];
            float go = ps[(12 | clu) * 68 + cb] + xg[3 * 256 + u0 + clu];
            c = sigf(gf) * c + sigf(gi) * tanhf(gg);
            g_h[dir][t][cb][u0 + clu] = sigf(go) * tanhf(c);
        }
        __threadfence();
        __syncthreads();
        if (tid == 0) {
            atomicAdd(&g_bar, 1u);
            unsigned tgt = (unsigned)(s + 1) * NBLK;
            while (ldcg(&g_bar) < tgt) {}
            (void)atomicAdd(&g_bar, 0u);   // coherent RMW confirm (R4 exit semantics)
            __threadfence();
        }
        __syncthreads();
    }
    if (tid == 0 && atomicAdd(&g_done, 1u) == NBLK - 1) {
        g_bar = 0u; g_done = 0u; __threadfence();
    }
}

// ============ Kernel 3: feats = [hf|hb] @ W_out.T + b_out ============
#define FE_SMEM ((64 * 520 + 34 * 520) * 4)
__global__ void __launch_bounds__(256, 1) feats_kernel(
    const float* __restrict__ W_out, const float* __restrict__ b_out)
{
    extern __shared__ float sm[];
    float* hc = sm;               // [64][520]
    float* wo = sm + 64 * 520;    // [34][520]
    int t = blockIdx.x, tid = threadIdx.x;
    for (int p = tid; p < 64 * 256; p += 256) {
        int b = p >> 8, k = p & 255;
        hc[b * 520 + k] = g_h[0][t][b][k];
        hc[b * 520 + 256 + k] = g_h[1][t][b][k];
    }
    for (int p = tid; p < 34 * 512; p += 256)
        wo[(p >> 9) * 520 + (p & 511)] = W_out[p];
    __syncthreads();
    for (int it = tid; it < 64 * 17; it += 256) {
        int b = it / 17, j0 = (it % 17) * 2, j1 = j0 + 1;
        ull a0 = 0, a1 = 0;
        const float* hp = hc + b * 520;
        const float* w0 = wo + j0 * 520;
        const float* w1 = wo + j1 * 520;
#pragma unroll 4
        for (int kp = 0; kp < 256; ++kp) {
            ull hv = *(const ull*)(hp + 2 * kp);
            a0 = ffma2(hv, *(const ull*)(w0 + 2 * kp), a0);
            a1 = ffma2(hv, *(const ull*)(w1 + 2 * kp), a1);
        }
        g_feats[t][b][j0] = hsum2(a0) + b_out[j0];
        g_feats[t][b][j1] = hsum2(a1) + b_out[j1];
    }
}

// ============ Kernel 4: Viterbi + backtrack (block per batch) ============
__global__ void __launch_bounds__(64) vit_kernel(
    const float* __restrict__ trans, float* out, int osz)
{
    __shared__ float tT[34 * 35];          // tT[j*35+k] = trans[k][j]
    __shared__ float dp[2][40];
    __shared__ unsigned char par[TT][34];
    int b = blockIdx.x, tid = threadIdx.x;
    for (int p = tid; p < 34 * 34; p += 64) tT[(p % 34) * 35 + (p / 34)] = trans[p];
    if (tid < 34) dp[0][tid] = (tid == 32) ? 0.f : NEGV;
    __syncthreads();

    float f = (tid < 34) ? g_feats[0][b][tid] : 0.f;
    int cur = 0;
    for (int t = 0; t < TT; ++t) {
        float fn = (tid < 34 && t < TT - 1) ? g_feats[t + 1][b][tid] : 0.f;
        if (tid < 34) {
            const float* tr = tT + tid * 35;
            const float* d = dp[cur];
            float be = d[0] + tr[0], bo = d[1] + tr[1];
            int ae = 0, ao = 1;
#pragma unroll
            for (int k = 2; k < 34; k += 2) {
                float ve = d[k] + tr[k];
                float vo = d[k + 1] + tr[k + 1];
                if (ve > be) { be = ve; ae = k; }
                if (vo > bo) { bo = vo; ao = k + 1; }
            }
            float best = be; int arg = ae;
            if (bo > be || (bo == be && ao < ae)) { best = bo; arg = ao; }
            par[t][tid] = (unsigned char)arg;
            dp[cur ^ 1][tid] = best + f;
        }
        f = fn;
        cur ^= 1;
        __syncthreads();
    }
    if (tid == 0) {
        float best = -1e30f; int lab = 0;
        const float* d = dp[cur];
        for (int j = 0; j < 34; ++j) {
            float v = d[j] + tT[33 * 35 + j];   // + trans[j][STOP]
            if (v > best) { best = v; lab = j; }
        }
        float* pp;
        if (osz >= BBATCH + BBATCH * TT) { out[b] = best; pp = out + BBATCH + (size_t)b * TT; }
        else if (osz >= BBATCH * TT)     { pp = out + (size_t)b * TT; }
        else                             { out[b] = best; return; }
        int l = lab;
        for (int t = TT - 1; t >= 0; --t) { pp[t] = (float)l; l = par[t][l]; }
    }
}

extern "C" void kernel_launch(void* const* d_in, const int* in_sizes, int n_in,
                              void* d_out, int out_size) {
    const int*   sent  = (const int*)d_in[0];
    const float* embed = (const float*)d_in[2];
    const float* Wih_f = (const float*)d_in[3];
    const float* Whh_f = (const float*)d_in[4];
    const float* bih_f = (const float*)d_in[5];
    const float* bhh_f = (const float*)d_in[6];
    const float* Wih_b = (const float*)d_in[7];
    const float* Whh_b = (const float*)d_in[8];
    const float* bih_b = (const float*)d_in[9];
    const float* bhh_b = (const float*)d_in[10];
    const float* h0    = (const float*)d_in[11];
    const float* c0    = (const float*)d_in[12];
    const float* W_out = (const float*)d_in[13];
    const float* b_out = (const float*)d_in[14];
    const float* trans = (const float*)d_in[15];

    cudaFuncSetAttribute(ig_kernel, cudaFuncAttributeMaxDynamicSharedMemorySize, IG_SMEM);
    cudaFuncSetAttribute(rec_kernel, cudaFuncAttributeMaxDynamicSharedMemorySize, REC_SMEM);
    cudaFuncSetAttribute(feats_kernel, cudaFuncAttributeMaxDynamicSharedMemorySize, FE_SMEM);

    ig_kernel<<<dim3(256, 16), 256, IG_SMEM>>>(sent, embed, Wih_f, Wih_b,
                                               bih_f, bhh_f, bih_b, bhh_b);
    rec_kernel<<<NBLK, 256, REC_SMEM>>>(Whh_f, Whh_b, h0, c0);
    feats_kernel<<<TT, 256, FE_SMEM>>>(W_out, b_out);
    vit_kernel<<<BBATCH, 64>>>(trans, (float*)d_out, out_size);
}

// round 11
// speedup vs baseline: 1.1030x; 1.0097x over previous
#include <cuda_runtime.h>
#include <cuda_bf16.h>
#include <math.h>

typedef unsigned long long ull;
#define TT 512
#define BBATCH 64
#define NLAB 34
#define NEGV -10000.0f
#define NBLK 128

__device__ float g_xg[2][TT][BBATCH][1024];
__device__ float g_h[2][TT][BBATCH][256];
__device__ float g_feats[TT][BBATCH][NLAB];
__device__ unsigned g_flag[NBLK];
__device__ unsigned g_d1 = 0, g_d2 = 0;

__device__ __forceinline__ ull ffma2(ull a, ull b, ull c) {
    ull d; asm("fma.rn.f32x2 %0,%1,%2,%3;" : "=l"(d) : "l"(a), "l"(b), "l"(c)); return d;
}
__device__ __forceinline__ float hsum2(ull a) {
    return __uint_as_float((unsigned)a) + __uint_as_float((unsigned)(a >> 32));
}
__device__ __forceinline__ float sigf(float x) { return 1.f / (1.f + expf(-x)); }
__device__ __forceinline__ unsigned ldcg(const unsigned* p) {
    unsigned v; asm volatile("ld.global.cg.u32 %0,[%1];" : "=r"(v) : "l"(p) : "memory");
    return v;
}
__device__ __forceinline__ void stcg(unsigned* p, unsigned v) {
    asm volatile("st.global.cg.u32 [%0],%1;" :: "l"(p), "r"(v) : "memory");
}

// ============ Kernel 1: embedding gather + input GEMM ============
#define IG_SMEM ((128 * 132 + 128 * 130) * 4)
__global__ void __launch_bounds__(256, 1) ig_kernel(
    const int* __restrict__ sent, const float* __restrict__ embed,
    const float* __restrict__ Wih_f, const float* __restrict__ Wih_b,
    const float* __restrict__ bih_f, const float* __restrict__ bhh_f,
    const float* __restrict__ bih_b, const float* __restrict__ bhh_b)
{
    extern __shared__ float sm[];
    float* As = sm;               // [128][132]
    float* Ws = sm + 128 * 132;   // [128][130]
    __shared__ int ssm[128];
    int tid = threadIdx.x;
    int row0 = blockIdx.x * 128, jg0 = blockIdx.y * 128;
    int dir = jg0 >> 10, col0 = jg0 & 1023;
    const float* W = dir ? Wih_b : Wih_f;
    const float* bA = dir ? bih_b : bih_f;
    const float* bB = dir ? bhh_b : bhh_f;
    if (tid < 128) { int r = row0 + tid; ssm[tid] = sent[(r & 63) * TT + (r >> 6)]; }

    ull acc[8][8];
#pragma unroll
    for (int i = 0; i < 8; ++i)
#pragma unroll
        for (int j = 0; j < 8; ++j) acc[i][j] = 0ull;
    int ty = tid >> 4, tx = tid & 15;

    for (int kc = 0; kc < 2; ++kc) {
        int k0 = kc * 128;
        __syncthreads();
#pragma unroll
        for (int it = 0; it < 16; ++it) {
            int idx = it * 256 + tid, r = idx >> 5, k4 = idx & 31;
            *(float4*)(As + r * 132 + k4 * 4) =
                *(const float4*)(embed + (size_t)ssm[r] * 256 + k0 + k4 * 4);
        }
#pragma unroll
        for (int it = 0; it < 16; ++it) {
            int idx = it * 256 + tid, c = idx >> 5, k4 = idx & 31;
            float4 v = *(const float4*)(W + (size_t)(col0 + c) * 256 + k0 + k4 * 4);
            *(float2*)(Ws + c * 130 + k4 * 4) = make_float2(v.x, v.y);
            *(float2*)(Ws + c * 130 + k4 * 4 + 2) = make_float2(v.z, v.w);
        }
        __syncthreads();
#pragma unroll 2
        for (int kp = 0; kp < 64; ++kp) {
            ull a[8], w[8];
#pragma unroll
            for (int i = 0; i < 8; ++i) a[i] = *(const ull*)(As + (ty + 16 * i) * 132 + kp * 2);
#pragma unroll
            for (int j = 0; j < 8; ++j) w[j] = *(const ull*)(Ws + (tx + 16 * j) * 130 + kp * 2);
#pragma unroll
            for (int i = 0; i < 8; ++i)
#pragma unroll
                for (int j = 0; j < 8; ++j) acc[i][j] = ffma2(a[i], w[j], acc[i][j]);
        }
    }
#pragma unroll
    for (int i = 0; i < 8; ++i) {
        int r = row0 + ty + 16 * i, t = r >> 6, b = r & 63;
#pragma unroll
        for (int j = 0; j < 8; ++j) {
            int c = col0 + tx + 16 * j;
            g_xg[dir][t][b][c] = hsum2(acc[i][j]) + bA[c] + bB[c];
        }
    }
}

// ============ Kernel 2: persistent BiLSTM recurrence ============
// R9 body; barrier replaced by per-direction FLAG ARRAY:
//   release: all threads __threadfence, __syncthreads, tid0 stores s+1 to g_flag[bid]
//   acquire: tid<64 each poll ONE flag of own direction, fence, __syncthreads.
// End protocol resets all globals to 0 (graph-replay deterministic).
#define REC_SMEM ((64 * 260 + 16 * 260 + 16 * 68) * 4)
__global__ void __launch_bounds__(256, 1) rec_kernel(
    const float* __restrict__ Whh_f, const float* __restrict__ Whh_b,
    const float* __restrict__ h0, const float* __restrict__ c0)
{
    extern __shared__ float sm[];
    float* hs = sm;                 // [64][260]
    float* ws = sm + 64 * 260;      // [16][260]
    float* ps = ws + 16 * 260;      // [16][68]
    int tid = threadIdx.x, bid = blockIdx.x;
    int dir = bid >> 6, u0 = (bid & 63) * 4;
    const float* W = dir ? Whh_b : Whh_f;

    for (int s = tid; s < 16 * 128; s += 256) {
        int rr = s >> 7, k2 = s & 127;
        *(float2*)(ws + rr * 260 + 2 * k2) =
            *(const float2*)(W + (size_t)((rr >> 2) * 256 + u0 + (rr & 3)) * 256 + 2 * k2);
    }
    int cb = tid & 63, clu = tid >> 6;                    // cell-update (b,lu)
    float c = c0[(dir * BBATCH + cb) * 256 + u0 + clu];
    int lane = tid & 31, wrp = tid >> 5;
    int rr = lane & 15, bh = lane >> 4;
    int b0 = bh * 32 + wrp * 4;                           // this thread: rr x b0..b0+3

    for (int s = 0; s < TT; ++s) {
        int t = dir ? TT - 1 - s : s;
        const float* hsrc = (s == 0) ? h0 + (size_t)dir * BBATCH * 256
                                     : &g_h[dir][dir ? t + 1 : t - 1][0][0];
        // prefetch this step's gate pre-activations (independent of barrier)
        const float* xg = &g_xg[dir][t][cb][0];
        float xi = xg[0 * 256 + u0 + clu];
        float xf = xg[1 * 256 + u0 + clu];
        float xG = xg[2 * 256 + u0 + clu];
        float xo = xg[3 * 256 + u0 + clu];

        for (int p = tid; p < 64 * 128; p += 256)
            *(float2*)(hs + (p >> 7) * 260 + 2 * (p & 127)) =
                *(const float2*)(hsrc + (p >> 7) * 256 + 2 * (p & 127));
        __syncthreads();
        {
            ull a0 = 0, a1 = 0, a2 = 0, a3 = 0;
            const float* wp = ws + rr * 260;
            const float* hp = hs + b0 * 260;
#pragma unroll 8
            for (int q = 0; q < 64; ++q) {
                ulonglong2 wv = *(const ulonglong2*)(wp + 4 * q);
                ulonglong2 h0v = *(const ulonglong2*)(hp + 4 * q);
                ulonglong2 h1v = *(const ulonglong2*)(hp + 260 + 4 * q);
                ulonglong2 h2v = *(const ulonglong2*)(hp + 520 + 4 * q);
                ulonglong2 h3v = *(const ulonglong2*)(hp + 780 + 4 * q);
                a0 = ffma2(h0v.x, wv.x, a0); a0 = ffma2(h0v.y, wv.y, a0);
                a1 = ffma2(h1v.x, wv.x, a1); a1 = ffma2(h1v.y, wv.y, a1);
                a2 = ffma2(h2v.x, wv.x, a2); a2 = ffma2(h2v.y, wv.y, a2);
                a3 = ffma2(h3v.x, wv.x, a3); a3 = ffma2(h3v.y, wv.y, a3);
            }
            ps[rr * 68 + b0] = hsum2(a0); ps[rr * 68 + b0 + 1] = hsum2(a1);
            ps[rr * 68 + b0 + 2] = hsum2(a2); ps[rr * 68 + b0 + 3] = hsum2(a3);
        }
        __syncthreads();
        {
            float gi = ps[(0 | clu) * 68 + cb] + xi;
            float gf = ps[(4 | clu) * 68 + cb] + xf;
            float gg = ps[(8 | clu) * 68 + cb] + xG;
            float go = ps[(12 | clu) * 68 + cb] + xo;
            c = sigf(gf) * c + sigf(gi) * tanhf(gg);
            g_h[dir][t][cb][u0 + clu] = sigf(go) * tanhf(c);
        }
        // ---- release ----
        __threadfence();
        __syncthreads();
        if (tid == 0) stcg(&g_flag[bid], (unsigned)(s + 1));
        // ---- acquire: poll own direction's 64 flags, one per thread ----
        if (tid < 64) {
            const unsigned* f = &g_flag[dir * 64 + tid];
            while (ldcg(f) < (unsigned)(s + 1)) {}
            __threadfence();
        }
        __syncthreads();
    }

    // ---- end protocol: reset all sync state to 0 for graph replay ----
    if (tid == 0) {
        atomicAdd(&g_d1, 1u);
        while (ldcg(&g_d1) < (unsigned)NBLK) {}   // all blocks done polling flags
        stcg(&g_flag[bid], 0u);
        __threadfence();
        unsigned o2 = atomicAdd(&g_d2, 1u);
        if (o2 == NBLK - 1u) { g_d1 = 0u; g_d2 = 0u; __threadfence(); }
    }
}

// ============ Kernel 3: feats = [hf|hb] @ W_out.T + b_out ============
#define FE_SMEM ((64 * 520 + 34 * 520) * 4)
__global__ void __launch_bounds__(256, 1) feats_kernel(
    const float* __restrict__ W_out, const float* __restrict__ b_out)
{
    extern __shared__ float sm[];
    float* hc = sm;               // [64][520]
    float* wo = sm + 64 * 520;    // [34][520]
    int t = blockIdx.x, tid = threadIdx.x;
    for (int p = tid; p < 64 * 256; p += 256) {
        int b = p >> 8, k = p & 255;
        hc[b * 520 + k] = g_h[0][t][b][k];
        hc[b * 520 + 256 + k] = g_h[1][t][b][k];
    }
    for (int p = tid; p < 34 * 512; p += 256)
        wo[(p >> 9) * 520 + (p & 511)] = W_out[p];
    __syncthreads();
    for (int it = tid; it < 64 * 17; it += 256) {
        int b = it / 17, j0 = (it % 17) * 2, j1 = j0 + 1;
        ull a0 = 0, a1 = 0;
        const float* hp = hc + b * 520;
        const float* w0 = wo + j0 * 520;
        const float* w1 = wo + j1 * 520;
#pragma unroll 4
        for (int kp = 0; kp < 256; ++kp) {
            ull hv = *(const ull*)(hp + 2 * kp);
            a0 = ffma2(hv, *(const ull*)(w0 + 2 * kp), a0);
            a1 = ffma2(hv, *(const ull*)(w1 + 2 * kp), a1);
        }
        g_feats[t][b][j0] = hsum2(a0) + b_out[j0];
        g_feats[t][b][j1] = hsum2(a1) + b_out[j1];
    }
}

// ============ Kernel 4: Viterbi + backtrack (block per batch) ============
__global__ void __launch_bounds__(64) vit_kernel(
    const float* __restrict__ trans, float* out, int osz)
{
    __shared__ float tT[34 * 35];          // tT[j*35+k] = trans[k][j]
    __shared__ float dp[2][40];
    __shared__ unsigned char par[TT][34];
    int b = blockIdx.x, tid = threadIdx.x;
    for (int p = tid; p < 34 * 34; p += 64) tT[(p % 34) * 35 + (p / 34)] = trans[p];
    if (tid < 34) dp[0][tid] = (tid == 32) ? 0.f : NEGV;
    __syncthreads();

    float f = (tid < 34) ? g_feats[0][b][tid] : 0.f;
    int cur = 0;
    for (int t = 0; t < TT; ++t) {
        float fn = (tid < 34 && t < TT - 1) ? g_feats[t + 1][b][tid] : 0.f;
        if (tid < 34) {
            const float* tr = tT + tid * 35;
            const float* d = dp[cur];
            float be = d[0] + tr[0], bo = d[1] + tr[1];
            int ae = 0, ao = 1;
#pragma unroll
            for (int k = 2; k < 34; k += 2) {
                float ve = d[k] + tr[k];
                float vo = d[k + 1] + tr[k + 1];
                if (ve > be) { be = ve; ae = k; }
                if (vo > bo) { bo = vo; ao = k + 1; }
            }
            float best = be; int arg = ae;
            if (bo > be || (bo == be && ao < ae)) { best = bo; arg = ao; }
            par[t][tid] = (unsigned char)arg;
            dp[cur ^ 1][tid] = best + f;
        }
        f = fn;
        cur ^= 1;
        __syncthreads();
    }
    if (tid == 0) {
        float best = -1e30f; int lab = 0;
        const float* d = dp[cur];
        for (int j = 0; j < 34; ++j) {
            float v = d[j] + tT[33 * 35 + j];   // + trans[j][STOP]
            if (v > best) { best = v; lab = j; }
        }
        float* pp;
        if (osz >= BBATCH + BBATCH * TT) { out[b] = best; pp = out + BBATCH + (size_t)b * TT; }
        else if (osz >= BBATCH * TT)     { pp = out + (size_t)b * TT; }
        else                             { out[b] = best; return; }
        int l = lab;
        for (int t = TT - 1; t >= 0; --t) { pp[t] = (float)l; l = par[t][l]; }
    }
}

extern "C" void kernel_launch(void* const* d_in, const int* in_sizes, int n_in,
                              void* d_out, int out_size) {
    const int*   sent  = (const int*)d_in[0];
    const float* embed = (const float*)d_in[2];
    const float* Wih_f = (const float*)d_in[3];
    const float* Whh_f = (const float*)d_in[4];
    const float* bih_f = (const float*)d_in[5];
    const float* bhh_f = (const float*)d_in[6];
    const float* Wih_b = (const float*)d_in[7];
    const float* Whh_b = (const float*)d_in[8];
    const float* bih_b = (const float*)d_in[9];
    const float* bhh_b = (const float*)d_in[10];
    const float* h0    = (const float*)d_in[11];
    const float* c0    = (const float*)d_in[12];
    const float* W_out = (const float*)d_in[13];
    const float* b_out = (const float*)d_in[14];
    const float* trans = (const float*)d_in[15];

    cudaFuncSetAttribute(ig_kernel, cudaFuncAttributeMaxDynamicSharedMemorySize, IG_SMEM);
    cudaFuncSetAttribute(rec_kernel, cudaFuncAttributeMaxDynamicSharedMemorySize, REC_SMEM);
    cudaFuncSetAttribute(feats_kernel, cudaFuncAttributeMaxDynamicSharedMemorySize, FE_SMEM);

    ig_kernel<<<dim3(256, 16), 256, IG_SMEM>>>(sent, embed, Wih_f, Wih_b,
                                               bih_f, bhh_f, bih_b, bhh_b);
    rec_kernel<<<NBLK, 256, REC_SMEM>>>(Whh_f, Whh_b, h0, c0);
    feats_kernel<<<TT, 256, FE_SMEM>>>(W_out, b_out);
    vit_kernel<<<BBATCH, 64>>>(trans, (float*)d_out, out_size);
}

// round 12
// speedup vs baseline: 1.2997x; 1.1783x over previous
#include <cuda_runtime.h>
#include <cuda_bf16.h>
#include <math.h>

typedef unsigned long long ull;
#define TT 512
#define BBATCH 64
#define NLAB 34
#define NEGV -10000.0f
#define NBLK 128

__device__ float g_xg[2][TT][BBATCH][1024];
__device__ float g_h[2][TT][BBATCH][256];
__device__ float g_feats[TT][BBATCH][NLAB];
__device__ unsigned g_flag[NBLK];
__device__ unsigned g_d1 = 0, g_d2 = 0;

__device__ __forceinline__ ull ffma2(ull a, ull b, ull c) {
    ull d; asm("fma.rn.f32x2 %0,%1,%2,%3;" : "=l"(d) : "l"(a), "l"(b), "l"(c)); return d;
}
__device__ __forceinline__ float hsum2(ull a) {
    return __uint_as_float((unsigned)a) + __uint_as_float((unsigned)(a >> 32));
}
__device__ __forceinline__ float sigf(float x) { return 1.f / (1.f + expf(-x)); }
__device__ __forceinline__ unsigned ldcg(const unsigned* p) {
    unsigned v; asm volatile("ld.global.cg.u32 %0,[%1];" : "=r"(v) : "l"(p) : "memory");
    return v;
}
__device__ __forceinline__ void stcg(unsigned* p, unsigned v) {
    asm volatile("st.global.cg.u32 [%0],%1;" :: "l"(p), "r"(v) : "memory");
}

// ============ Kernel 1: embedding gather + input GEMM ============
#define IG_SMEM ((128 * 132 + 128 * 130) * 4)
__global__ void __launch_bounds__(256, 1) ig_kernel(
    const int* __restrict__ sent, const float* __restrict__ embed,
    const float* __restrict__ Wih_f, const float* __restrict__ Wih_b,
    const float* __restrict__ bih_f, const float* __restrict__ bhh_f,
    const float* __restrict__ bih_b, const float* __restrict__ bhh_b)
{
    extern __shared__ float sm[];
    float* As = sm;               // [128][132]
    float* Ws = sm + 128 * 132;   // [128][130]
    __shared__ int ssm[128];
    int tid = threadIdx.x;
    int row0 = blockIdx.x * 128, jg0 = blockIdx.y * 128;
    int dir = jg0 >> 10, col0 = jg0 & 1023;
    const float* W = dir ? Wih_b : Wih_f;
    const float* bA = dir ? bih_b : bih_f;
    const float* bB = dir ? bhh_b : bhh_f;
    if (tid < 128) { int r = row0 + tid; ssm[tid] = sent[(r & 63) * TT + (r >> 6)]; }

    ull acc[8][8];
#pragma unroll
    for (int i = 0; i < 8; ++i)
#pragma unroll
        for (int j = 0; j < 8; ++j) acc[i][j] = 0ull;
    int ty = tid >> 4, tx = tid & 15;

    for (int kc = 0; kc < 2; ++kc) {
        int k0 = kc * 128;
        __syncthreads();
#pragma unroll
        for (int it = 0; it < 16; ++it) {
            int idx = it * 256 + tid, r = idx >> 5, k4 = idx & 31;
            *(float4*)(As + r * 132 + k4 * 4) =
                *(const float4*)(embed + (size_t)ssm[r] * 256 + k0 + k4 * 4);
        }
#pragma unroll
        for (int it = 0; it < 16; ++it) {
            int idx = it * 256 + tid, c = idx >> 5, k4 = idx & 31;
            float4 v = *(const float4*)(W + (size_t)(col0 + c) * 256 + k0 + k4 * 4);
            *(float2*)(Ws + c * 130 + k4 * 4) = make_float2(v.x, v.y);
            *(float2*)(Ws + c * 130 + k4 * 4 + 2) = make_float2(v.z, v.w);
        }
        __syncthreads();
#pragma unroll 2
        for (int kp = 0; kp < 64; ++kp) {
            ull a[8], w[8];
#pragma unroll
            for (int i = 0; i < 8; ++i) a[i] = *(const ull*)(As + (ty + 16 * i) * 132 + kp * 2);
#pragma unroll
            for (int j = 0; j < 8; ++j) w[j] = *(const ull*)(Ws + (tx + 16 * j) * 130 + kp * 2);
#pragma unroll
            for (int i = 0; i < 8; ++i)
#pragma unroll
                for (int j = 0; j < 8; ++j) acc[i][j] = ffma2(a[i], w[j], acc[i][j]);
        }
    }
#pragma unroll
    for (int i = 0; i < 8; ++i) {
        int r = row0 + ty + 16 * i, t = r >> 6, b = r & 63;
#pragma unroll
        for (int j = 0; j < 8; ++j) {
            int c = col0 + tx + 16 * j;
            g_xg[dir][t][b][c] = hsum2(acc[i][j]) + bA[c] + bB[c];
        }
    }
}

// ============ Kernel 2: persistent BiLSTM recurrence (512 threads/block) ============
// 128 blocks: dir=bid>>6, block owns 4 units (16 gate rows rr=(g<<2)|lu).
// 16 warps: warps 0-7 cover k[0,128) (kh=0), warps 8-15 k[128,256) (kh=1);
// partial sums ps[kh][rr][b], summed in cell update. Flag barrier unchanged.
#define REC_SMEM ((64 * 260 + 16 * 260 + 2 * 16 * 68) * 4)
__global__ void __launch_bounds__(512, 1) rec_kernel(
    const float* __restrict__ Whh_f, const float* __restrict__ Whh_b,
    const float* __restrict__ h0, const float* __restrict__ c0)
{
    extern __shared__ float sm[];
    float* hs = sm;                 // [64][260]
    float* ws = sm + 64 * 260;      // [16][260]
    float* ps = ws + 16 * 260;      // [2][16][68]
    int tid = threadIdx.x, bid = blockIdx.x;
    int dir = bid >> 6, u0 = (bid & 63) * 4;
    const float* W = dir ? Whh_b : Whh_f;

    for (int s = tid; s < 16 * 128; s += 512) {
        int rr = s >> 7, k2 = s & 127;
        *(float2*)(ws + rr * 260 + 2 * k2) =
            *(const float2*)(W + (size_t)((rr >> 2) * 256 + u0 + (rr & 3)) * 256 + 2 * k2);
    }
    int cb = tid & 63, clu = (tid >> 6) & 3;              // cell-update (b,lu), tid<256
    float c = (tid < 256) ? c0[(dir * BBATCH + cb) * 256 + u0 + clu] : 0.f;
    int lane = tid & 31, wrp = (tid >> 5) & 7, kh = tid >> 8;
    int rr = lane & 15, bh = lane >> 4;
    int b0 = bh * 32 + wrp * 4;                           // thread: rr x b0..b0+3, k-half kh

    for (int s = 0; s < TT; ++s) {
        int t = dir ? TT - 1 - s : s;
        const float* hsrc = (s == 0) ? h0 + (size_t)dir * BBATCH * 256
                                     : &g_h[dir][dir ? t + 1 : t - 1][0][0];
        // prefetch this step's gate pre-activations (independent of barrier)
        float xi = 0.f, xf = 0.f, xG = 0.f, xo = 0.f;
        if (tid < 256) {
            const float* xg = &g_xg[dir][t][cb][0];
            xi = xg[0 * 256 + u0 + clu];
            xf = xg[1 * 256 + u0 + clu];
            xG = xg[2 * 256 + u0 + clu];
            xo = xg[3 * 256 + u0 + clu];
        }

        for (int p = tid; p < 64 * 128; p += 512)
            *(float2*)(hs + (p >> 7) * 260 + 2 * (p & 127)) =
                *(const float2*)(hsrc + (p >> 7) * 256 + 2 * (p & 127));
        __syncthreads();
        {
            ull a0 = 0, a1 = 0, a2 = 0, a3 = 0;
            const float* wp = ws + rr * 260 + kh * 128;
            const float* hp = hs + b0 * 260 + kh * 128;
#pragma unroll 8
            for (int q = 0; q < 32; ++q) {
                ulonglong2 wv = *(const ulonglong2*)(wp + 4 * q);
                ulonglong2 h0v = *(const ulonglong2*)(hp + 4 * q);
                ulonglong2 h1v = *(const ulonglong2*)(hp + 260 + 4 * q);
                ulonglong2 h2v = *(const ulonglong2*)(hp + 520 + 4 * q);
                ulonglong2 h3v = *(const ulonglong2*)(hp + 780 + 4 * q);
                a0 = ffma2(h0v.x, wv.x, a0); a0 = ffma2(h0v.y, wv.y, a0);
                a1 = ffma2(h1v.x, wv.x, a1); a1 = ffma2(h1v.y, wv.y, a1);
                a2 = ffma2(h2v.x, wv.x, a2); a2 = ffma2(h2v.y, wv.y, a2);
                a3 = ffma2(h3v.x, wv.x, a3); a3 = ffma2(h3v.y, wv.y, a3);
            }
            float* pr = ps + (kh * 16 + rr) * 68;
            pr[b0] = hsum2(a0); pr[b0 + 1] = hsum2(a1);
            pr[b0 + 2] = hsum2(a2); pr[b0 + 3] = hsum2(a3);
        }
        __syncthreads();
        if (tid < 256) {
            float gi = ps[clu * 68 + cb]        + ps[(16 + clu) * 68 + cb]        + xi;
            float gf = ps[(4 | clu) * 68 + cb]  + ps[(16 + (4 | clu)) * 68 + cb]  + xf;
            float gg = ps[(8 | clu) * 68 + cb]  + ps[(16 + (8 | clu)) * 68 + cb]  + xG;
            float go = ps[(12 | clu) * 68 + cb] + ps[(16 + (12 | clu)) * 68 + cb] + xo;
            c = sigf(gf) * c + sigf(gi) * tanhf(gg);
            g_h[dir][t][cb][u0 + clu] = sigf(go) * tanhf(c);
        }
        // ---- release ----
        __threadfence();
        __syncthreads();
        if (tid == 0) stcg(&g_flag[bid], (unsigned)(s + 1));
        // ---- acquire: poll own direction's 64 flags, one per thread ----
        if (tid < 64) {
            const unsigned* f = &g_flag[dir * 64 + tid];
            while (ldcg(f) < (unsigned)(s + 1)) {}
            __threadfence();
        }
        __syncthreads();
    }

    // ---- end protocol: reset all sync state to 0 for graph replay ----
    if (tid == 0) {
        atomicAdd(&g_d1, 1u);
        while (ldcg(&g_d1) < (unsigned)NBLK) {}
        stcg(&g_flag[bid], 0u);
        __threadfence();
        unsigned o2 = atomicAdd(&g_d2, 1u);
        if (o2 == NBLK - 1u) { g_d1 = 0u; g_d2 = 0u; __threadfence(); }
    }
}

// ============ Kernel 3: feats = [hf|hb] @ W_out.T + b_out ============
#define FE_SMEM ((64 * 520 + 34 * 520) * 4)
__global__ void __launch_bounds__(256, 1) feats_kernel(
    const float* __restrict__ W_out, const float* __restrict__ b_out)
{
    extern __shared__ float sm[];
    float* hc = sm;               // [64][520]
    float* wo = sm + 64 * 520;    // [34][520]
    int t = blockIdx.x, tid = threadIdx.x;
    for (int p = tid; p < 64 * 256; p += 256) {
        int b = p >> 8, k = p & 255;
        hc[b * 520 + k] = g_h[0][t][b][k];
        hc[b * 520 + 256 + k] = g_h[1][t][b][k];
    }
    for (int p = tid; p < 34 * 512; p += 256)
        wo[(p >> 9) * 520 + (p & 511)] = W_out[p];
    __syncthreads();
    for (int it = tid; it < 64 * 17; it += 256) {
        int b = it / 17, j0 = (it % 17) * 2, j1 = j0 + 1;
        ull a0 = 0, a1 = 0;
        const float* hp = hc + b * 520;
        const float* w0 = wo + j0 * 520;
        const float* w1 = wo + j1 * 520;
#pragma unroll 4
        for (int kp = 0; kp < 256; ++kp) {
            ull hv = *(const ull*)(hp + 2 * kp);
            a0 = ffma2(hv, *(const ull*)(w0 + 2 * kp), a0);
            a1 = ffma2(hv, *(const ull*)(w1 + 2 * kp), a1);
        }
        g_feats[t][b][j0] = hsum2(a0) + b_out[j0];
        g_feats[t][b][j1] = hsum2(a1) + b_out[j1];
    }
}

// ============ Kernel 4: Viterbi + backtrack (block per batch) ============
__global__ void __launch_bounds__(64) vit_kernel(
    const float* __restrict__ trans, float* out, int osz)
{
    __shared__ float tT[34 * 35];          // tT[j*35+k] = trans[k][j]
    __shared__ float dp[2][40];
    __shared__ unsigned char par[TT][34];
    int b = blockIdx.x, tid = threadIdx.x;
    for (int p = tid; p < 34 * 34; p += 64) tT[(p % 34) * 35 + (p / 34)] = trans[p];
    if (tid < 34) dp[0][tid] = (tid == 32) ? 0.f : NEGV;
    __syncthreads();

    float f = (tid < 34) ? g_feats[0][b][tid] : 0.f;
    int cur = 0;
    for (int t = 0; t < TT; ++t) {
        float fn = (tid < 34 && t < TT - 1) ? g_feats[t + 1][b][tid] : 0.f;
        if (tid < 34) {
            const float* tr = tT + tid * 35;
            const float* d = dp[cur];
            float be = d[0] + tr[0], bo = d[1] + tr[1];
            int ae = 0, ao = 1;
#pragma unroll
            for (int k = 2; k < 34; k += 2) {
                float ve = d[k] + tr[k];
                float vo = d[k + 1] + tr[k + 1];
                if (ve > be) { be = ve; ae = k; }
                if (vo > bo) { bo = vo; ao = k + 1; }
            }
            float best = be; int arg = ae;
            if (bo > be || (bo == be && ao < ae)) { best = bo; arg = ao; }
            par[t][tid] = (unsigned char)arg;
            dp[cur ^ 1][tid] = best + f;
        }
        f = fn;
        cur ^= 1;
        __syncthreads();
    }
    if (tid == 0) {
        float best = -1e30f; int lab = 0;
        const float* d = dp[cur];
        for (int j = 0; j < 34; ++j) {
            float v = d[j] + tT[33 * 35 + j];   // + trans[j][STOP]
            if (v > best) { best = v; lab = j; }
        }
        float* pp;
        if (osz >= BBATCH + BBATCH * TT) { out[b] = best; pp = out + BBATCH + (size_t)b * TT; }
        else if (osz >= BBATCH * TT)     { pp = out + (size_t)b * TT; }
        else                             { out[b] = best; return; }
        int l = lab;
        for (int t = TT - 1; t >= 0; --t) { pp[t] = (float)l; l = par[t][l]; }
    }
}

extern "C" void kernel_launch(void* const* d_in, const int* in_sizes, int n_in,
                              void* d_out, int out_size) {
    const int*   sent  = (const int*)d_in[0];
    const float* embed = (const float*)d_in[2];
    const float* Wih_f = (const float*)d_in[3];
    const float* Whh_f = (const float*)d_in[4];
    const float* bih_f = (const float*)d_in[5];
    const float* bhh_f = (const float*)d_in[6];
    const float* Wih_b = (const float*)d_in[7];
    const float* Whh_b = (const float*)d_in[8];
    const float* bih_b = (const float*)d_in[9];
    const float* bhh_b = (const float*)d_in[10];
    const float* h0    = (const float*)d_in[11];
    const float* c0    = (const float*)d_in[12];
    const float* W_out = (const float*)d_in[13];
    const float* b_out = (const float*)d_in[14];
    const float* trans = (const float*)d_in[15];

    cudaFuncSetAttribute(ig_kernel, cudaFuncAttributeMaxDynamicSharedMemorySize, IG_SMEM);
    cudaFuncSetAttribute(rec_kernel, cudaFuncAttributeMaxDynamicSharedMemorySize, REC_SMEM);
    cudaFuncSetAttribute(feats_kernel, cudaFuncAttributeMaxDynamicSharedMemorySize, FE_SMEM);

    ig_kernel<<<dim3(256, 16), 256, IG_SMEM>>>(sent, embed, Wih_f, Wih_b,
                                               bih_f, bhh_f, bih_b, bhh_b);
    rec_kernel<<<NBLK, 512, REC_SMEM>>>(Whh_f, Whh_b, h0, c0);
    feats_kernel<<<TT, 256, FE_SMEM>>>(W_out, b_out);
    vit_kernel<<<BBATCH, 64>>>(trans, (float*)d_out, out_size);
}

// round 13
// speedup vs baseline: 1.3438x; 1.0339x over previous
#include <cuda_runtime.h>
#include <cuda_bf16.h>
#include <math.h>

typedef unsigned long long ull;
#define TT 512
#define BBATCH 64
#define NLAB 34
#define NEGV -10000.0f
#define NBLK 128

__device__ float g_xg[2][TT][BBATCH][1024];
__device__ float g_h[2][TT][BBATCH][256];
__device__ float g_feats[TT][BBATCH][NLAB];
__device__ unsigned g_flag[NBLK];
__device__ unsigned g_d1 = 0, g_d2 = 0;

__device__ __forceinline__ ull ffma2(ull a, ull b, ull c) {
    ull d; asm("fma.rn.f32x2 %0,%1,%2,%3;" : "=l"(d) : "l"(a), "l"(b), "l"(c)); return d;
}
__device__ __forceinline__ float hsum2(ull a) {
    return __uint_as_float((unsigned)a) + __uint_as_float((unsigned)(a >> 32));
}
__device__ __forceinline__ float sigf(float x) { return 1.f / (1.f + expf(-x)); }
__device__ __forceinline__ unsigned ldcg(const unsigned* p) {
    unsigned v; asm volatile("ld.global.cg.u32 %0,[%1];" : "=r"(v) : "l"(p) : "memory");
    return v;
}
__device__ __forceinline__ void stcg(unsigned* p, unsigned v) {
    asm volatile("st.global.cg.u32 [%0],%1;" :: "l"(p), "r"(v) : "memory");
}

// ============ Kernel 1: embedding gather + input GEMM ============
#define IG_SMEM ((128 * 132 + 128 * 130) * 4)
__global__ void __launch_bounds__(256, 1) ig_kernel(
    const int* __restrict__ sent, const float* __restrict__ embed,
    const float* __restrict__ Wih_f, const float* __restrict__ Wih_b,
    const float* __restrict__ bih_f, const float* __restrict__ bhh_f,
    const float* __restrict__ bih_b, const float* __restrict__ bhh_b)
{
    extern __shared__ float sm[];
    float* As = sm;               // [128][132]
    float* Ws = sm + 128 * 132;   // [128][130]
    __shared__ int ssm[128];
    int tid = threadIdx.x;
    int row0 = blockIdx.x * 128, jg0 = blockIdx.y * 128;
    int dir = jg0 >> 10, col0 = jg0 & 1023;
    const float* W = dir ? Wih_b : Wih_f;
    const float* bA = dir ? bih_b : bih_f;
    const float* bB = dir ? bhh_b : bhh_f;
    if (tid < 128) { int r = row0 + tid; ssm[tid] = sent[(r & 63) * TT + (r >> 6)]; }

    ull acc[8][8];
#pragma unroll
    for (int i = 0; i < 8; ++i)
#pragma unroll
        for (int j = 0; j < 8; ++j) acc[i][j] = 0ull;
    int ty = tid >> 4, tx = tid & 15;

    for (int kc = 0; kc < 2; ++kc) {
        int k0 = kc * 128;
        __syncthreads();
#pragma unroll
        for (int it = 0; it < 16; ++it) {
            int idx = it * 256 + tid, r = idx >> 5, k4 = idx & 31;
            *(float4*)(As + r * 132 + k4 * 4) =
                *(const float4*)(embed + (size_t)ssm[r] * 256 + k0 + k4 * 4);
        }
#pragma unroll
        for (int it = 0; it < 16; ++it) {
            int idx = it * 256 + tid, c = idx >> 5, k4 = idx & 31;
            float4 v = *(const float4*)(W + (size_t)(col0 + c) * 256 + k0 + k4 * 4);
            *(float2*)(Ws + c * 130 + k4 * 4) = make_float2(v.x, v.y);
            *(float2*)(Ws + c * 130 + k4 * 4 + 2) = make_float2(v.z, v.w);
        }
        __syncthreads();
#pragma unroll 2
        for (int kp = 0; kp < 64; ++kp) {
            ull a[8], w[8];
#pragma unroll
            for (int i = 0; i < 8; ++i) a[i] = *(const ull*)(As + (ty + 16 * i) * 132 + kp * 2);
#pragma unroll
            for (int j = 0; j < 8; ++j) w[j] = *(const ull*)(Ws + (tx + 16 * j) * 130 + kp * 2);
#pragma unroll
            for (int i = 0; i < 8; ++i)
#pragma unroll
                for (int j = 0; j < 8; ++j) acc[i][j] = ffma2(a[i], w[j], acc[i][j]);
        }
    }
#pragma unroll
    for (int i = 0; i < 8; ++i) {
        int r = row0 + ty + 16 * i, t = r >> 6, b = r & 63;
#pragma unroll
        for (int j = 0; j < 8; ++j) {
            int c = col0 + tx + 16 * j;
            g_xg[dir][t][b][c] = hsum2(acc[i][j]) + bA[c] + bB[c];
        }
    }
}

// ============ Kernel 2: persistent BiLSTM recurrence (1024 threads/block) ============
// 128 blocks: dir=bid>>6, block owns 4 units (16 gate rows rr=(g<<2)|lu).
// 32 warps; kq = tid>>8 in {0..3} covers k-quarter [kq*64,(kq+1)*64);
// partial sums ps[kq][rr][b], summed (4-way) in cell update. Flag barrier unchanged.
#define REC_SMEM ((64 * 260 + 16 * 260 + 4 * 16 * 68) * 4)
__global__ void __launch_bounds__(1024, 1) rec_kernel(
    const float* __restrict__ Whh_f, const float* __restrict__ Whh_b,
    const float* __restrict__ h0, const float* __restrict__ c0)
{
    extern __shared__ float sm[];
    float* hs = sm;                 // [64][260]
    float* ws = sm + 64 * 260;      // [16][260]
    float* ps = ws + 16 * 260;      // [4][16][68]
    int tid = threadIdx.x, bid = blockIdx.x;
    int dir = bid >> 6, u0 = (bid & 63) * 4;
    const float* W = dir ? Whh_b : Whh_f;

    for (int s = tid; s < 16 * 128; s += 1024) {
        int rr = s >> 7, k2 = s & 127;
        *(float2*)(ws + rr * 260 + 2 * k2) =
            *(const float2*)(W + (size_t)((rr >> 2) * 256 + u0 + (rr & 3)) * 256 + 2 * k2);
    }
    int cb = tid & 63, clu = (tid >> 6) & 3;              // cell-update (b,lu), tid<256
    float c = (tid < 256) ? c0[(dir * BBATCH + cb) * 256 + u0 + clu] : 0.f;
    int lane = tid & 31, wrp = (tid >> 5) & 7, kq = tid >> 8;   // k-quarter
    int rr = lane & 15, bh = lane >> 4;
    int b0 = bh * 32 + wrp * 4;                           // thread: rr x b0..b0+3, quarter kq

    for (int s = 0; s < TT; ++s) {
        int t = dir ? TT - 1 - s : s;
        const float* hsrc = (s == 0) ? h0 + (size_t)dir * BBATCH * 256
                                     : &g_h[dir][dir ? t + 1 : t - 1][0][0];
        // prefetch this step's gate pre-activations (independent of barrier)
        float xi = 0.f, xf = 0.f, xG = 0.f, xo = 0.f;
        if (tid < 256) {
            const float* xg = &g_xg[dir][t][cb][0];
            xi = xg[0 * 256 + u0 + clu];
            xf = xg[1 * 256 + u0 + clu];
            xG = xg[2 * 256 + u0 + clu];
            xo = xg[3 * 256 + u0 + clu];
        }

        for (int p = tid; p < 64 * 128; p += 1024)
            *(float2*)(hs + (p >> 7) * 260 + 2 * (p & 127)) =
                *(const float2*)(hsrc + (p >> 7) * 256 + 2 * (p & 127));
        __syncthreads();
        {
            ull a0 = 0, a1 = 0, a2 = 0, a3 = 0;
            const float* wp = ws + rr * 260 + kq * 64;
            const float* hp = hs + b0 * 260 + kq * 64;
#pragma unroll
            for (int q = 0; q < 16; ++q) {
                ulonglong2 wv = *(const ulonglong2*)(wp + 4 * q);
                ulonglong2 h0v = *(const ulonglong2*)(hp + 4 * q);
                ulonglong2 h1v = *(const ulonglong2*)(hp + 260 + 4 * q);
                ulonglong2 h2v = *(const ulonglong2*)(hp + 520 + 4 * q);
                ulonglong2 h3v = *(const ulonglong2*)(hp + 780 + 4 * q);
                a0 = ffma2(h0v.x, wv.x, a0); a0 = ffma2(h0v.y, wv.y, a0);
                a1 = ffma2(h1v.x, wv.x, a1); a1 = ffma2(h1v.y, wv.y, a1);
                a2 = ffma2(h2v.x, wv.x, a2); a2 = ffma2(h2v.y, wv.y, a2);
                a3 = ffma2(h3v.x, wv.x, a3); a3 = ffma2(h3v.y, wv.y, a3);
            }
            float* pr = ps + (kq * 16 + rr) * 68;
            pr[b0] = hsum2(a0); pr[b0 + 1] = hsum2(a1);
            pr[b0 + 2] = hsum2(a2); pr[b0 + 3] = hsum2(a3);
        }
        __syncthreads();
        if (tid < 256) {
            float gi = xi, gf = xf, gg = xG, go = xo;
#pragma unroll
            for (int k = 0; k < 4; ++k) {
                gi += ps[(k * 16 + (0 | clu)) * 68 + cb];
                gf += ps[(k * 16 + (4 | clu)) * 68 + cb];
                gg += ps[(k * 16 + (8 | clu)) * 68 + cb];
                go += ps[(k * 16 + (12 | clu)) * 68 + cb];
            }
            c = sigf(gf) * c + sigf(gi) * tanhf(gg);
            g_h[dir][t][cb][u0 + clu] = sigf(go) * tanhf(c);
        }
        // ---- release ----
        __threadfence();
        __syncthreads();
        if (tid == 0) stcg(&g_flag[bid], (unsigned)(s + 1));
        // ---- acquire: poll own direction's 64 flags, one per thread ----
        if (tid < 64) {
            const unsigned* f = &g_flag[dir * 64 + tid];
            while (ldcg(f) < (unsigned)(s + 1)) {}
            __threadfence();
        }
        __syncthreads();
    }

    // ---- end protocol: reset all sync state to 0 for graph replay ----
    if (tid == 0) {
        atomicAdd(&g_d1, 1u);
        while (ldcg(&g_d1) < (unsigned)NBLK) {}
        stcg(&g_flag[bid], 0u);
        __threadfence();
        unsigned o2 = atomicAdd(&g_d2, 1u);
        if (o2 == NBLK - 1u) { g_d1 = 0u; g_d2 = 0u; __threadfence(); }
    }
}

// ============ Kernel 3: feats = [hf|hb] @ W_out.T + b_out ============
#define FE_SMEM ((64 * 520 + 34 * 520) * 4)
__global__ void __launch_bounds__(256, 1) feats_kernel(
    const float* __restrict__ W_out, const float* __restrict__ b_out)
{
    extern __shared__ float sm[];
    float* hc = sm;               // [64][520]
    float* wo = sm + 64 * 520;    // [34][520]
    int t = blockIdx.x, tid = threadIdx.x;
    for (int p = tid; p < 64 * 256; p += 256) {
        int b = p >> 8, k = p & 255;
        hc[b * 520 + k] = g_h[0][t][b][k];
        hc[b * 520 + 256 + k] = g_h[1][t][b][k];
    }
    for (int p = tid; p < 34 * 512; p += 256)
        wo[(p >> 9) * 520 + (p & 511)] = W_out[p];
    __syncthreads();
    for (int it = tid; it < 64 * 17; it += 256) {
        int b = it / 17, j0 = (it % 17) * 2, j1 = j0 + 1;
        ull a0 = 0, a1 = 0;
        const float* hp = hc + b * 520;
        const float* w0 = wo + j0 * 520;
        const float* w1 = wo + j1 * 520;
#pragma unroll 4
        for (int kp = 0; kp < 256; ++kp) {
            ull hv = *(const ull*)(hp + 2 * kp);
            a0 = ffma2(hv, *(const ull*)(w0 + 2 * kp), a0);
            a1 = ffma2(hv, *(const ull*)(w1 + 2 * kp), a1);
        }
        g_feats[t][b][j0] = hsum2(a0) + b_out[j0];
        g_feats[t][b][j1] = hsum2(a1) + b_out[j1];
    }
}

// ============ Kernel 4: Viterbi + backtrack (block per batch) ============
__global__ void __launch_bounds__(64) vit_kernel(
    const float* __restrict__ trans, float* out, int osz)
{
    __shared__ float tT[34 * 35];          // tT[j*35+k] = trans[k][j]
    __shared__ float dp[2][40];
    __shared__ unsigned char par[TT][34];
    int b = blockIdx.x, tid = threadIdx.x;
    for (int p = tid; p < 34 * 34; p += 64) tT[(p % 34) * 35 + (p / 34)] = trans[p];
    if (tid < 34) dp[0][tid] = (tid == 32) ? 0.f : NEGV;
    __syncthreads();

    float f = (tid < 34) ? g_feats[0][b][tid] : 0.f;
    int cur = 0;
    for (int t = 0; t < TT; ++t) {
        float fn = (tid < 34 && t < TT - 1) ? g_feats[t + 1][b][tid] : 0.f;
        if (tid < 34) {
            const float* tr = tT + tid * 35;
            const float* d = dp[cur];
            float be = d[0] + tr[0], bo = d[1] + tr[1];
            int ae = 0, ao = 1;
#pragma unroll
            for (int k = 2; k < 34; k += 2) {
                float ve = d[k] + tr[k];
                float vo = d[k + 1] + tr[k + 1];
                if (ve > be) { be = ve; ae = k; }
                if (vo > bo) { bo = vo; ao = k + 1; }
            }
            float best = be; int arg = ae;
            if (bo > be || (bo == be && ao < ae)) { best = bo; arg = ao; }
            par[t][tid] = (unsigned char)arg;
            dp[cur ^ 1][tid] = best + f;
        }
        f = fn;
        cur ^= 1;
        __syncthreads();
    }
    if (tid == 0) {
        float best = -1e30f; int lab = 0;
        const float* d = dp[cur];
        for (int j = 0; j < 34; ++j) {
            float v = d[j] + tT[33 * 35 + j];   // + trans[j][STOP]
            if (v > best) { best = v; lab = j; }
        }
        float* pp;
        if (osz >= BBATCH + BBATCH * TT) { out[b] = best; pp = out + BBATCH + (size_t)b * TT; }
        else if (osz >= BBATCH * TT)     { pp = out + (size_t)b * TT; }
        else                             { out[b] = best; return; }
        int l = lab;
        for (int t = TT - 1; t >= 0; --t) { pp[t] = (float)l; l = par[t][l]; }
    }
}

extern "C" void kernel_launch(void* const* d_in, const int* in_sizes, int n_in,
                              void* d_out, int out_size) {
    const int*   sent  = (const int*)d_in[0];
    const float* embed = (const float*)d_in[2];
    const float* Wih_f = (const float*)d_in[3];
    const float* Whh_f = (const float*)d_in[4];
    const float* bih_f = (const float*)d_in[5];
    const float* bhh_f = (const float*)d_in[6];
    const float* Wih_b = (const float*)d_in[7];
    const float* Whh_b = (const float*)d_in[8];
    const float* bih_b = (const float*)d_in[9];
    const float* bhh_b = (const float*)d_in[10];
    const float* h0    = (const float*)d_in[11];
    const float* c0    = (const float*)d_in[12];
    const float* W_out = (const float*)d_in[13];
    const float* b_out = (const float*)d_in[14];
    const float* trans = (const float*)d_in[15];

    cudaFuncSetAttribute(ig_kernel, cudaFuncAttributeMaxDynamicSharedMemorySize, IG_SMEM);
    cudaFuncSetAttribute(rec_kernel, cudaFuncAttributeMaxDynamicSharedMemorySize, REC_SMEM);
    cudaFuncSetAttribute(feats_kernel, cudaFuncAttributeMaxDynamicSharedMemorySize, FE_SMEM);

    ig_kernel<<<dim3(256, 16), 256, IG_SMEM>>>(sent, embed, Wih_f, Wih_b,
                                               bih_f, bhh_f, bih_b, bhh_b);
    rec_kernel<<<NBLK, 1024, REC_SMEM>>>(Whh_f, Whh_b, h0, c0);
    feats_kernel<<<TT, 256, FE_SMEM>>>(W_out, b_out);
    vit_kernel<<<BBATCH, 64>>>(trans, (float*)d_out, out_size);
}